// round 17
// baseline (speedup 1.0000x reference)
#include <cuda_runtime.h>
#include <cuda_bf16.h>
#include <cstdint>

// GRU dims
#define Bdim  128
#define Tdim  512
#define Idim  512
#define Hdim  1024
#define G3    3072
#define MTOT  65536
#define NCTA  128

// ---- recurrence smem layout (bytes): W 96KB + A ring 3x32KB ----
#define R_BHI   0
#define R_BLO   49152
#define R_A     98304
#define R_AH(s) (R_A + (s) * 32768)
#define R_AL(s) (R_A + (s) * 32768 + 16384)
#define SMEM_REC (R_A + 3 * 32768)          // 196608

// ---- phase A smem layout ----
#define PA_AH(buf) ((buf) * 65536 + 0)
#define PA_AL(buf) ((buf) * 65536 + 16384)
#define PA_BH(buf) ((buf) * 65536 + 32768)
#define PA_BL(buf) ((buf) * 65536 + 49152)
#define PA_SMEM    131072

// Scratch (static __device__ — no allocations allowed)
__device__ float g_fi[(size_t)MTOT * G3];               // [T][B][3H]
__device__ __nv_bfloat16 g_ah[(size_t)MTOT * Idim];     // inputs hi
__device__ __nv_bfloat16 g_al[(size_t)MTOT * Idim];     // inputs lo
__device__ __nv_bfloat16 g_wh[(size_t)G3 * Idim];       // W_in^T hi  [n][k]
__device__ __nv_bfloat16 g_wl[(size_t)G3 * Idim];       // W_in^T lo
__device__ __nv_bfloat16 g_hh[(size_t)Bdim * Hdim];     // h hi
__device__ __nv_bfloat16 g_hl[(size_t)Bdim * Hdim];     // h lo
__device__ unsigned g_bar[Tdim];

__device__ __forceinline__ float sigmoidf_fast(float x) {
  return 1.0f / (1.0f + __expf(-x));
}

// ---------- grid barrier ----------
__device__ __forceinline__ void bar_arrive(unsigned* p) {
  asm volatile("red.release.gpu.global.add.u32 [%0], 1;" :: "l"(p) : "memory");
}
__device__ __forceinline__ unsigned bar_peek(const unsigned* p) {
  unsigned v;
  asm volatile("ld.acquire.gpu.global.u32 %0, [%1];" : "=r"(v) : "l"(p) : "memory");
  return v;
}

// ---------- HMMA / ldmatrix / cp.async ----------
__device__ __forceinline__ uint32_t smem_u32(const void* p) {
  uint32_t a;
  asm("{ .reg .u64 t; cvta.to.shared.u64 t, %1; cvt.u32.u64 %0, t; }" : "=r"(a) : "l"(p));
  return a;
}
#define LDSM_X4(r, a) \
  asm volatile("ldmatrix.sync.aligned.m8n8.x4.shared.b16 {%0,%1,%2,%3}, [%4];" \
    : "=r"((r)[0]), "=r"((r)[1]), "=r"((r)[2]), "=r"((r)[3]) : "r"(a))
#define LDSM_X2(r, a) \
  asm volatile("ldmatrix.sync.aligned.m8n8.x2.shared.b16 {%0,%1}, [%2];" \
    : "=r"((r)[0]), "=r"((r)[1]) : "r"(a))

__device__ __forceinline__ void mma16816(float* d, const uint32_t* a,
                                         uint32_t b0, uint32_t b1) {
  asm volatile(
    "mma.sync.aligned.m16n8k16.row.col.f32.bf16.bf16.f32 "
    "{%0,%1,%2,%3}, {%4,%5,%6,%7}, {%8,%9}, {%0,%1,%2,%3};"
    : "+f"(d[0]), "+f"(d[1]), "+f"(d[2]), "+f"(d[3])
    : "r"(a[0]), "r"(a[1]), "r"(a[2]), "r"(a[3]), "r"(b0), "r"(b1));
}

__device__ __forceinline__ void cp16(uint32_t dst, const void* src) {
  asm volatile("cp.async.cg.shared.global [%0], [%1], 16;" :: "r"(dst), "l"(src));
}
#define CP_COMMIT() asm volatile("cp.async.commit_group;" ::: "memory")
#define CP_WAIT0()  asm volatile("cp.async.wait_group 0;" ::: "memory")
#define CP_WAIT1()  asm volatile("cp.async.wait_group 1;" ::: "memory")

// =====================================================================
__global__ void reset_kernel() { g_bar[threadIdx.x] = 0u; }

// =====================================================================
// Convert inputs -> bf16 hi/lo
// =====================================================================
__global__ void __launch_bounds__(256) conv_in_kernel(const float* __restrict__ x) {
  size_t i = ((size_t)blockIdx.x * 256 + threadIdx.x) * 2;
  float2 v = *(const float2*)(x + i);
  __nv_bfloat16 h0 = __float2bfloat16_rn(v.x);
  __nv_bfloat16 h1 = __float2bfloat16_rn(v.y);
  __nv_bfloat16 l0 = __float2bfloat16_rn(v.x - __bfloat162float(h0));
  __nv_bfloat16 l1 = __float2bfloat16_rn(v.y - __bfloat162float(h1));
  *(__nv_bfloat162*)(g_ah + i) = __nv_bfloat162(h0, h1);
  *(__nv_bfloat162*)(g_al + i) = __nv_bfloat162(l0, l1);
}

// =====================================================================
// Convert + transpose W_in [K=512][N=3072] -> g_wh/g_wl [N][K] hi/lo
// =====================================================================
__global__ void __launch_bounds__(256) conv_w_kernel(const float* __restrict__ W) {
  __shared__ float tile[32][33];
  const int tx = threadIdx.x & 31;
  const int ty = threadIdx.x >> 5;
  const int kb = blockIdx.y * 32;
  const int nb = blockIdx.x * 32;
#pragma unroll
  for (int i = 0; i < 4; i++)
    tile[ty + i * 8][tx] = W[(size_t)(kb + ty + i * 8) * G3 + nb + tx];
  __syncthreads();
#pragma unroll
  for (int i = 0; i < 4; i++) {
    int n = nb + ty + i * 8;
    int k = kb + tx;
    float v = tile[tx][ty + i * 8];
    __nv_bfloat16 h = __float2bfloat16_rn(v);
    g_wh[(size_t)n * Idim + k] = h;
    g_wl[(size_t)n * Idim + k] = __float2bfloat16_rn(v - __bfloat162float(h));
  }
}

// =====================================================================
// Phase A (HMMA): g_fi[t][b][n] = inputs@W_in + bias_in, split-bf16 3-pass.
// =====================================================================
__global__ void __launch_bounds__(256) gemm_fi_mma_kernel(
    const float* __restrict__ bias)
{
  extern __shared__ __align__(1024) char smem[];
  const uint32_t sb = smem_u32(smem);
  const int tid = threadIdx.x;
  const int w   = tid >> 5;
  const int l   = tid & 31;
  const int mw  = w & 1;
  const int nw  = w >> 1;
  const int bm  = blockIdx.y * 128;
  const int bn  = blockIdx.x * 128;

  const int srow = tid >> 3;
  const int sq   = tid & 7;
  const uint32_t soff0 = (uint32_t)srow * 128 + (((uint32_t)sq * 16) ^ (((uint32_t)srow & 7) << 4));

  float acc[4][4][4];
#pragma unroll
  for (int mt = 0; mt < 4; mt++)
#pragma unroll
    for (int nt = 0; nt < 4; nt++)
#pragma unroll
      for (int j = 0; j < 4; j++) acc[mt][nt][j] = 0.0f;

  const uint32_t PAr = (uint32_t)(((l & 7) + ((l >> 3) & 1) * 8)) * 128;
  const uint32_t QA  = ((uint32_t)((l >> 4) & 1) * 16) ^ (((uint32_t)l & 7) << 4);
  const uint32_t PBr = (uint32_t)(((l & 7) + ((l >> 4) & 1) * 8)) * 128;
  const uint32_t QB  = ((uint32_t)((l >> 3) & 1) * 16) ^ (((uint32_t)l & 7) << 4);

  auto stage = [&](int buf, int kb) {
#pragma unroll
    for (int q4 = 0; q4 < 4; q4++) {
      int row = srow + q4 * 32;
      uint32_t so = soff0 + (uint32_t)q4 * 32 * 128;
      const size_t asrc = (size_t)(bm + row) * Idim + kb + sq * 8;
      const size_t bsrc = (size_t)(bn + row) * Idim + kb + sq * 8;
      cp16(sb + PA_AH(buf) + so, g_ah + asrc);
      cp16(sb + PA_AL(buf) + so, g_al + asrc);
      cp16(sb + PA_BH(buf) + so, g_wh + bsrc);
      cp16(sb + PA_BL(buf) + so, g_wl + bsrc);
    }
  };

  stage(0, 0);
  CP_COMMIT();
  CP_WAIT0();
  __syncthreads();

  for (int kt = 0; kt < 8; kt++) {
    const int buf = kt & 1;
    if (kt < 7) { stage(buf ^ 1, (kt + 1) * 64); CP_COMMIT(); }

    const uint32_t ah_b = sb + PA_AH(buf) + (uint32_t)(mw * 64) * 128 + PAr;
    const uint32_t al_b = sb + PA_AL(buf) + (uint32_t)(mw * 64) * 128 + PAr;
    const uint32_t bh_b = sb + PA_BH(buf) + (uint32_t)(nw * 32) * 128 + PBr;
    const uint32_t bl_b = sb + PA_BL(buf) + (uint32_t)(nw * 32) * 128 + PBr;

#pragma unroll
    for (int kk = 0; kk < 4; kk++) {
      const uint32_t ao = ((uint32_t)kk * 32) ^ QA;
      const uint32_t bo = ((uint32_t)kk * 32) ^ QB;
      uint32_t Ah[4][4], Al[4][4];
#pragma unroll
      for (int mt = 0; mt < 4; mt++) {
        LDSM_X4(Ah[mt], ah_b + (uint32_t)(mt * 16) * 128 + ao);
        LDSM_X4(Al[mt], al_b + (uint32_t)(mt * 16) * 128 + ao);
      }
#pragma unroll
      for (int ntp = 0; ntp < 2; ntp++) {
        uint32_t Bh[4], Bl[4];
        LDSM_X4(Bh, bh_b + (uint32_t)(ntp * 16) * 128 + bo);
        LDSM_X4(Bl, bl_b + (uint32_t)(ntp * 16) * 128 + bo);
#pragma unroll
        for (int mt = 0; mt < 4; mt++) {
          mma16816(acc[mt][ntp * 2],     Ah[mt], Bh[0], Bh[1]);
          mma16816(acc[mt][ntp * 2 + 1], Ah[mt], Bh[2], Bh[3]);
          mma16816(acc[mt][ntp * 2],     Ah[mt], Bl[0], Bl[1]);
          mma16816(acc[mt][ntp * 2 + 1], Ah[mt], Bl[2], Bl[3]);
          mma16816(acc[mt][ntp * 2],     Al[mt], Bh[0], Bh[1]);
          mma16816(acc[mt][ntp * 2 + 1], Al[mt], Bh[2], Bh[3]);
        }
      }
    }

    if (kt < 7) CP_WAIT0();
    __syncthreads();
  }

  const int quad = l >> 2;
  const int cq   = (l & 3) * 2;
#pragma unroll
  for (int nt = 0; nt < 4; nt++) {
    const int col = bn + nw * 32 + nt * 8 + cq;
    const float2 bv = *(const float2*)(bias + col);
#pragma unroll
    for (int mt = 0; mt < 4; mt++) {
      int m0 = bm + mw * 64 + mt * 16 + quad;
#pragma unroll
      for (int half = 0; half < 2; half++) {
        int m  = m0 + half * 8;
        int b  = m >> 9;
        int tt = m & (Tdim - 1);
        *(float2*)(g_fi + ((size_t)tt * Bdim + b) * G3 + col) =
            make_float2(acc[mt][nt][half * 2] + bv.x, acc[mt][nt][half * 2 + 1] + bv.y);
      }
    }
  }
}

// =====================================================================
// Persistent HMMA recurrence: 128 CTAs x 256 threads.
// cp.async 3-stage ring; ONE sync per ring iteration (mid-sync removed:
// slot (i+2)%3 reuse is ordered by the head sync of iteration i).
// =====================================================================
__global__ void __launch_bounds__(256, 1) recurrence_kernel(
    const float* __restrict__ Wh,     // [Hdim, G3]
    const float* __restrict__ bias,   // [6H]
    float* __restrict__ out)          // hseq [B,T,H] then h_last [B,H]
{
  extern __shared__ __align__(1024) char smem[];
  const uint32_t sb = smem_u32(smem);
  const int tid = threadIdx.x;
  const int w   = tid >> 5;
  const int l   = tid & 31;
  const int c   = blockIdx.x;
  const int cb  = c * 8;

  // ---- Stage W slice (transposed, split hi/lo) once ----
  for (int idx = tid; idx < 24 * 1024; idx += 256) {
    int n = idx >> 10;
    int k = idx & 1023;
    float wv = Wh[(size_t)k * G3 + (n >> 3) * Hdim + cb + (n & 7)];
    __nv_bfloat16 hi = __float2bfloat16_rn(wv);
    __nv_bfloat16 lo = __float2bfloat16_rn(wv - __bfloat162float(hi));
    int row = n & 7;
    uint32_t off = (uint32_t)(((k >> 6) * 3 + (n >> 3)) * 1024 + row * 128 +
                              ((((k & 63) * 2)) ^ (row << 4)));
    *(__nv_bfloat16*)(smem + R_BHI + off) = hi;
    *(__nv_bfloat16*)(smem + R_BLO + off) = lo;
  }
  __syncthreads();

  const int arow = w * 16 + (l & 7) + ((l >> 3) & 1) * 8;
  const uint32_t QA = ((uint32_t)((l >> 4) & 1) * 16) ^ (((uint32_t)arow & 7) << 4);
  const uint32_t PAr = (uint32_t)arow * 128;
  const int brow = l & 7;
  const int bnt  = (l >> 4) & 1;
  const uint32_t QB = ((uint32_t)((l >> 3) & 1) * 16) ^ ((uint32_t)brow << 4);
  const uint32_t PBr = (uint32_t)bnt * 1024 + (uint32_t)brow * 128;

  const int srow = tid >> 3;
  const int sq   = tid & 7;

  const int quad = l >> 2;
  const int c0   = (l & 3) * 2;
  const int bA   = w * 16 + quad;
  const int bB   = bA + 8;

  float bh[3][2];
#pragma unroll
  for (int g = 0; g < 3; g++) {
    bh[g][0] = bias[G3 + g * Hdim + cb + c0];
    bh[g][1] = bias[G3 + g * Hdim + cb + c0 + 1];
  }

  float hreg[2][2] = {{0.f, 0.f}, {0.f, 0.f}};

  for (int t = 0; t < Tdim; t++) {
    float2 fi[2][3];
#pragma unroll
    for (int bi = 0; bi < 2; bi++) {
      const int b = bi ? bB : bA;
      const float* fb = g_fi + ((size_t)t * Bdim + b) * G3 + cb + c0;
#pragma unroll
      for (int g = 0; g < 3; g++)
        fi[bi][g] = __ldg((const float2*)(fb + g * Hdim));
    }

    float d[3][4];
#pragma unroll
    for (int g = 0; g < 3; g++)
#pragma unroll
      for (int j = 0; j < 4; j++) d[g][j] = 0.0f;

    if (t > 0) {
      auto stageA = [&](int slot, int tile) {
        const int kb = tile * 64;
#pragma unroll
        for (int q4 = 0; q4 < 4; q4++) {
          int b = srow + q4 * 32;
          uint32_t so = (uint32_t)b * 128 + (((uint32_t)sq * 16) ^ (((uint32_t)b & 7) << 4));
          cp16(sb + R_AH(slot) + so, g_hh + (size_t)b * Hdim + kb + sq * 8);
          cp16(sb + R_AL(slot) + so, g_hl + (size_t)b * Hdim + kb + sq * 8);
        }
      };

      // prologue: tiles 0 and 1 in flight
      stageA(0, 0); CP_COMMIT();
      stageA(1, 1); CP_COMMIT();

      for (int i = 0; i < 16; i++) {
        const int slot = i % 3;
        // wait for tile i (tile i+1 may stay in flight)
        if (i < 15) CP_WAIT1(); else CP_WAIT0();
        __syncthreads();

        // issue tile i+2 into slot (i+2)%3 = tile i-1's slot.
        // Safe: all readers of tile i-1 crossed the sync above before this issue.
        if (i < 14) { stageA((i + 2) % 3, i + 2); CP_COMMIT(); }

        const uint32_t pa_hi = sb + R_AH(slot) + PAr;
        const uint32_t pa_lo = sb + R_AL(slot) + PAr;
        const uint32_t pb_hi = sb + R_BHI + (uint32_t)i * 3072 + PBr;
        const uint32_t pb_lo = sb + R_BLO + (uint32_t)i * 3072 + PBr;
        const uint32_t pb2_hi = sb + R_BHI + (uint32_t)i * 3072 + 2048 + (uint32_t)brow * 128;
        const uint32_t pb2_lo = sb + R_BLO + (uint32_t)i * 3072 + 2048 + (uint32_t)brow * 128;

#pragma unroll
        for (int kk = 0; kk < 4; kk++) {
          const uint32_t ao = ((uint32_t)kk * 32) ^ QA;
          const uint32_t bo = ((uint32_t)kk * 32) ^ QB;
          uint32_t Ah[4], Al[4], Bh[4], Bl[4], B2h[2], B2l[2];
          LDSM_X4(Ah, pa_hi + ao);
          LDSM_X4(Al, pa_lo + ao);
          LDSM_X4(Bh, pb_hi + bo);
          LDSM_X4(Bl, pb_lo + bo);
          LDSM_X2(B2h, pb2_hi + bo);
          LDSM_X2(B2l, pb2_lo + bo);
          // interleaved accumulators: reuse distance 3
          mma16816(d[0], Ah, Bh[0], Bh[1]);
          mma16816(d[1], Ah, Bh[2], Bh[3]);
          mma16816(d[2], Ah, B2h[0], B2h[1]);
          mma16816(d[0], Ah, Bl[0], Bl[1]);
          mma16816(d[1], Ah, Bl[2], Bl[3]);
          mma16816(d[2], Ah, B2l[0], B2l[1]);
          mma16816(d[0], Al, Bh[0], Bh[1]);
          mma16816(d[1], Al, Bh[2], Bh[3]);
          mma16816(d[2], Al, B2h[0], B2h[1]);
        }
      }
    }

#pragma unroll
    for (int bi = 0; bi < 2; bi++) {
      const int b = bi ? bB : bA;
      float hv[2];
#pragma unroll
      for (int j = 0; j < 2; j++) {
        float fr = (j ? fi[bi][0].y : fi[bi][0].x);
        float fz = (j ? fi[bi][1].y : fi[bi][1].x);
        float fn = (j ? fi[bi][2].y : fi[bi][2].x);
        float rr = sigmoidf_fast(fr + d[0][bi * 2 + j] + bh[0][j]);
        float zz = sigmoidf_fast(fz + d[1][bi * 2 + j] + bh[1][j]);
        float nn = tanhf(fn + rr * (d[2][bi * 2 + j] + bh[2][j]));
        hv[j] = (1.0f - zz) * nn + zz * hreg[bi][j];
        hreg[bi][j] = hv[j];
      }
      *(float2*)(out + ((size_t)b * Tdim + t) * Hdim + cb + c0) = make_float2(hv[0], hv[1]);
      __nv_bfloat162 h2 = __floats2bfloat162_rn(hv[0], hv[1]);
      float l0 = hv[0] - __bfloat162float(__float2bfloat16_rn(hv[0]));
      float l1 = hv[1] - __bfloat162float(__float2bfloat16_rn(hv[1]));
      __nv_bfloat162 l2 = __floats2bfloat162_rn(l0, l1);
      *(__nv_bfloat162*)(g_hh + (size_t)b * Hdim + cb + c0) = h2;
      *(__nv_bfloat162*)(g_hl + (size_t)b * Hdim + cb + c0) = l2;
      if (t == Tdim - 1) {
        *(float2*)(out + (size_t)Bdim * Tdim * Hdim + (size_t)b * Hdim + cb + c0) =
            make_float2(hv[0], hv[1]);
      }
    }

    if (t < Tdim - 1) {
      __syncthreads();
      if (tid == 0) {
        bar_arrive(&g_bar[t]);
        while (bar_peek(&g_bar[t]) < NCTA) { __nanosleep(32); }
      }
      __syncthreads();
    }
  }
}

// =====================================================================
extern "C" void kernel_launch(void* const* d_in, const int* in_sizes, int n_in,
                              void* d_out, int out_size) {
  (void)in_sizes; (void)n_in; (void)out_size;
  const float* inputs = (const float*)d_in[0];
  const float* W_in   = (const float*)d_in[1];
  const float* W_h    = (const float*)d_in[2];
  const float* bias   = (const float*)d_in[3];
  float* out = (float*)d_out;

  static int attr_set = 0;
  if (!attr_set) {
    cudaFuncSetAttribute(recurrence_kernel,
                         cudaFuncAttributeMaxDynamicSharedMemorySize, SMEM_REC);
    cudaFuncSetAttribute(gemm_fi_mma_kernel,
                         cudaFuncAttributeMaxDynamicSharedMemorySize, PA_SMEM);
    attr_set = 1;
  }

  reset_kernel<<<1, Tdim>>>();
  conv_in_kernel<<<(int)((size_t)MTOT * Idim / 2 / 256), 256>>>(inputs);
  {
    dim3 grid(G3 / 32, Idim / 32);
    conv_w_kernel<<<grid, 256>>>(W_in);
  }
  {
    dim3 grid(G3 / 128, MTOT / 128);
    gemm_fi_mma_kernel<<<grid, 256, PA_SMEM>>>(bias);
  }
  recurrence_kernel<<<NCTA, 256, SMEM_REC>>>(W_h, bias, out);
}